// round 6
// baseline (speedup 1.0000x reference)
#include <cuda_runtime.h>
#include <cstdint>

// Upscale2d: 2x zero-insert upsample + 4x4 binomial FIR == separable 2-tap
// polyphase: even (a + 3b)/4, odd (3b + c)/4 per axis.
// x: [8,64,256,256] f32 -> y: [8,64,512,512] f32, zero-padded borders.
//
// Each CTA produces a 16x512 output tile (32KB) for one plane: computed into
// SMEM with shuffle-based horizontal combines, then emitted as ONE
// cp.async.bulk (TMA bulk store) of 32KB -> full-line writes, no
// fill-on-write, perfectly sequential DRAM bursts.

#define IN_H 256
#define IN_W 256
#define OUT_W 512
#define RPT 8   // input rows per CTA
#define RPH 4   // input rows per 128-thread half

__global__ __launch_bounds__(256) void upscale2d_kernel(
    const float* __restrict__ x, float* __restrict__ y)
{
    __shared__ __align__(128) float tile[2 * RPT * OUT_W];  // 16*512 f32 = 32KB

    const int t    = threadIdx.x & 127;   // owns input cols [2t, 2t+1]
    const int half = threadIdx.x >> 7;    // 0/1
    const int lane = threadIdx.x & 31;
    const int gb   = blockIdx.x;          // row block 0..31
    const int p    = blockIdx.y;          // plane (N*C)

    const int c0 = 2 * t;
    const float* xp = x + (size_t)p * IN_H * IN_W;
    const int rb = gb * RPT;              // CTA input row base
    const int r0 = rb + half * RPH;       // half input row base

    const bool edgeL = (lane == 0)  && (c0 >= 1);
    const bool edgeR = (lane == 31) && (c0 + 2 < IN_W);

    // raw row load (zero outside [0, IN_H)); e = cross-warp edge element
    auto loadraw = [&](int r, float& e) -> float2 {
        e = 0.f;
        if (r < 0 || r >= IN_H) return make_float2(0.f, 0.f);
        const float* row = xp + (size_t)r * IN_W;
        if (edgeL) e = __ldg(row + c0 - 1);
        if (edgeR) e = __ldg(row + c0 + 2);
        return *(const float2*)(row + c0);
    };

    // horizontal pre-combines
    auto comb = [&](float2 c, float e,
                    float& H0, float& O0, float& H1, float& O1) {
        float l  = __shfl_up_sync(0xffffffffu, c.y, 1);   // col c0-1
        float rr = __shfl_down_sync(0xffffffffu, c.x, 1); // col c0+2
        if (lane == 0)  l  = e;
        if (lane == 31) rr = e;
        H0 = l   + 3.f * c.x;  O0 = 3.f * c.x + c.y;
        H1 = c.x + 3.f * c.y;  O1 = 3.f * c.y + rr;
    };

    float eP, eN;
    float2 rprev = loadraw(r0 - 1, eP);
    float2 rnext = loadraw(r0, eN);

    float pH0, pO0, pH1, pO1;
    comb(rprev, eP, pH0, pO0, pH1, pO1);

    #pragma unroll
    for (int i = 0; i <= RPH; i++) {
        const int r = r0 + i;

        // next iteration's load first (latency cover)
        float eF = 0.f;
        float2 rfut = make_float2(0.f, 0.f);
        if (i < RPH) rfut = loadraw(r + 1, eF);

        float cH0, cO0, cH1, cO1;
        comb(rnext, eN, cH0, cO0, cH1, cO1);

        // tile row = global output row - 2*rb
        if (i > 0) {
            float4 v;
            v.x = (3.f * pH0 + cH0) * 0.0625f;
            v.y = (3.f * pO0 + cO0) * 0.0625f;
            v.z = (3.f * pH1 + cH1) * 0.0625f;
            v.w = (3.f * pO1 + cO1) * 0.0625f;
            int s = 2 * r - 1 - 2 * rb;
            *(float4*)(tile + s * OUT_W + 2 * c0) = v;
        }
        if (i < RPH) {
            float4 v;
            v.x = (pH0 + 3.f * cH0) * 0.0625f;
            v.y = (pO0 + 3.f * cO0) * 0.0625f;
            v.z = (pH1 + 3.f * cH1) * 0.0625f;
            v.w = (pO1 + 3.f * cO1) * 0.0625f;
            int s = 2 * r - 2 * rb;
            *(float4*)(tile + s * OUT_W + 2 * c0) = v;
        }

        pH0 = cH0; pO0 = cO0; pH1 = cH1; pO1 = cO1;
        rnext = rfut; eN = eF;
    }

    __syncthreads();

    if (threadIdx.x == 0) {
        // order generic smem writes before the async-proxy bulk read
        asm volatile("fence.proxy.async.shared::cta;" ::: "memory");
        float* dst = y + (size_t)p * OUT_W * OUT_W + (size_t)(2 * rb) * OUT_W;
        uint32_t saddr;
        asm volatile("{ .reg .u64 ta; cvta.to.shared.u64 ta, %1; cvt.u32.u64 %0, ta; }"
                     : "=r"(saddr) : "l"(tile));
        asm volatile("cp.async.bulk.global.shared::cta.bulk_group [%0], [%1], %2;"
                     :: "l"(dst), "r"(saddr), "n"(2 * RPT * OUT_W * 4) : "memory");
        asm volatile("cp.async.bulk.commit_group;" ::: "memory");
        // smem must stay live until the bulk read completes
        asm volatile("cp.async.bulk.wait_group.read 0;" ::: "memory");
    }
    __syncthreads();
}

extern "C" void kernel_launch(void* const* d_in, const int* in_sizes, int n_in,
                              void* d_out, int out_size)
{
    const float* x = (const float*)d_in[0];
    float* y = (float*)d_out;
    int planes = in_sizes[0] / (IN_H * IN_W);            // 512
    dim3 grid(IN_H / RPT, planes);                       // (32, 512)
    upscale2d_kernel<<<grid, 256>>>(x, y);
}